// round 7
// baseline (speedup 1.0000x reference)
#include <cuda_runtime.h>
#include <cuda_bf16.h>
#include <math.h>

// Problem constants
#define B_     64
#define S_     2048
#define D_     768
#define L_     2
#define POOL_  30
#define LEN_   5
#define TOPK_  5
#define SS_    16           // S split count
#define SCHUNK_ (S_ / SS_)  // 128

// Output layout (flattened tuple, fp32):
#define NB_ELEMS   (L_ * B_ * (TOPK_*LEN_) * D_)   // 2457600
#define OFF_SB     0
#define OFF_TB     (NB_ELEMS)
#define OFF_SSIM   (2 * NB_ELEMS)
#define OFF_TSIM   (OFF_SSIM + B_ * POOL_)
#define OFF_SRED   (OFF_TSIM + B_ * POOL_)
#define OFF_TRED   (OFF_SRED + 1)

// Device scratch
__device__ float g_partial[SS_ * B_ * D_];   // 3 MB partial sums
__device__ float g_stop[B_];
__device__ float g_ttop[B_];
__device__ int   g_bctr[B_];                 // per-batch arrival counters (self-reset)
__device__ int   g_done;                     // batch-completion counter (self-reset)

// ---------------------------------------------------------------------------
// Single fused kernel.
// Phase 1 (all 1024 blocks): partial mean of one (b, ss) chunk.
// Phase 2 (last block per b): reduce partials -> normalize -> 60 sims ->
//          top-5 -> gather batch b's prompts; last of 64 emits scalars.
// No block ever waits on another block: the continuation runs only on the
// last arriver, so the kernel cannot deadlock regardless of scheduling.
// ---------------------------------------------------------------------------
__global__ void __launch_bounds__(192) k_fused(const float* __restrict__ x,
                                               const float* __restrict__ skey,
                                               const float* __restrict__ tkey,
                                               const float* __restrict__ sp,
                                               const float* __restrict__ tp,
                                               float* __restrict__ out) {
    // Shared layout: 16B-aligned vector array FIRST.
    __shared__ __align__(16) float xn[D_];
    __shared__ float sim[2 * POOL_];
    __shared__ float red[8];
    __shared__ float stop2[2];
    __shared__ int   sidx[2][TOPK_];
    __shared__ int   slast;

    const int b  = blockIdx.x;
    const int ss = blockIdx.y;
    const int d4 = threadIdx.x;               // 0..191, each owns 4 d's

    // ---- Phase 1: streaming partial sum ----
    {
        const float4* xp = reinterpret_cast<const float4*>(x)
                         + ((size_t)(b * S_ + ss * SCHUNK_)) * (D_ / 4) + d4;
        float4 acc = make_float4(0.f, 0.f, 0.f, 0.f);
#pragma unroll 16
        for (int s = 0; s < SCHUNK_; ++s) {
            float4 v = __ldcs(&xp[(size_t)s * (D_ / 4)]);
            acc.x += v.x; acc.y += v.y; acc.z += v.z; acc.w += v.w;
        }
        reinterpret_cast<float4*>(g_partial)[(ss * B_ + b) * (D_ / 4) + d4] = acc;
    }

    // ---- Publish + arrival counter: last block of batch b continues ----
    __threadfence();                          // all threads publish their stores
    __syncthreads();
    if (threadIdx.x == 0) {
        int old = atomicAdd(&g_bctr[b], 1);
        slast = (old == SS_ - 1);
        if (old == SS_ - 1) atomicExch(&g_bctr[b], 0);   // self-reset for replay
    }
    __syncthreads();
    if (!slast) return;
    __threadfence();                          // acquire side: see all partials

    // ---- Phase 2: finalize batch b (192 threads, 6 warps) ----

    // mean over 16 partials; accumulate |x_mean|^2
    float sq;
    {
        float4 s = make_float4(0.f, 0.f, 0.f, 0.f);
#pragma unroll
        for (int s2 = 0; s2 < SS_; ++s2) {
            float4 v = reinterpret_cast<const float4*>(g_partial)[(s2 * B_ + b) * (D_ / 4) + d4];
            s.x += v.x; s.y += v.y; s.z += v.z; s.w += v.w;
        }
        const float scale = 1.f / (float)S_;
        s.x *= scale; s.y *= scale; s.z *= scale; s.w *= scale;
        reinterpret_cast<float4*>(xn)[d4] = s;
        sq = s.x * s.x + s.y * s.y + s.z * s.z + s.w * s.w;
    }

    // block reduce over 6 warps
    const int lane = threadIdx.x & 31, w = threadIdx.x >> 5;
#pragma unroll
    for (int o = 16; o; o >>= 1) sq += __shfl_down_sync(0xffffffffu, sq, o);
    if (lane == 0) red[w] = sq;
    __syncthreads();
    float total;
    {
        float v = (w == 0 && lane < 6) ? red[lane] : 0.f;
        if (w == 0) {
#pragma unroll
            for (int o = 4; o; o >>= 1) v += __shfl_down_sync(0xffffffffu, v, o);
            if (lane == 0) red[0] = v;
        }
        __syncthreads();
        total = red[0];
    }
    const float inv = rsqrtf(fmaxf(total, 1e-12f));
    {
        float4 v = reinterpret_cast<float4*>(xn)[d4];
        v.x *= inv; v.y *= inv; v.z *= inv; v.w *= inv;
        reinterpret_cast<float4*>(xn)[d4] = v;
    }
    __syncthreads();

    // 60 dots: warp per key, round-robin over 6 warps; inline key norm
    for (int key = w; key < 2 * POOL_; key += 6) {
        const float* kp = (key < POOL_) ? (skey + key * D_)
                                        : (tkey + (key - POOL_) * D_);
        float dot = 0.f, kk = 0.f;
#pragma unroll
        for (int i = 0; i < D_ / 32; ++i) {
            int d = lane + i * 32;
            float kv = __ldg(&kp[d]);
            dot += kv * xn[d];
            kk  += kv * kv;
        }
#pragma unroll
        for (int o = 16; o; o >>= 1) {
            dot += __shfl_down_sync(0xffffffffu, dot, o);
            kk  += __shfl_down_sync(0xffffffffu, kk, o);
        }
        if (lane == 0) {
            float sv = dot * rsqrtf(fmaxf(kk, 1e-12f));
            sim[key] = sv;
            if (key < POOL_) out[OFF_SSIM + b * POOL_ + key] = sv;
            else             out[OFF_TSIM + b * POOL_ + (key - POOL_)] = sv;
        }
    }
    __syncthreads();

    // top-5 (threads 0 and 1 into shared); strict '>' keeps lowest index on ties
    if (threadIdx.x < 2) {
        const float* sm = sim + threadIdx.x * POOL_;
        float loc[POOL_];
#pragma unroll
        for (int i = 0; i < POOL_; ++i) loc[i] = sm[i];
        float topsum = 0.f;
#pragma unroll
        for (int k = 0; k < TOPK_; ++k) {
            int   bj = 0;
            float bv = loc[0];
#pragma unroll
            for (int i = 1; i < POOL_; ++i) {
                if (loc[i] > bv) { bv = loc[i]; bj = i; }
            }
            sidx[threadIdx.x][k] = bj;
            topsum += bv;
            loc[bj] = -INFINITY;
        }
        stop2[threadIdx.x] = topsum;
    }
    __syncthreads();

    // thread 0 alone publishes both per-batch sums, then fence + arrival;
    // the 64th arriver computes the scalars (reads via L2 to avoid stale L1).
    if (threadIdx.x == 0) {
        g_stop[b] = stop2[0];
        g_ttop[b] = stop2[1];
        __threadfence();
        int old = atomicAdd(&g_done, 1);
        if (old == B_ - 1) {
            atomicExch(&g_done, 0);           // self-reset for replay
            __threadfence();
            float s0 = 0.f, s1 = 0.f;
            for (int i = 0; i < B_; ++i) {
                s0 += __ldcg(&g_stop[i]);
                s1 += __ldcg(&g_ttop[i]);
            }
            out[OFF_SRED] = s0 / (float)B_;
            out[OFF_TRED] = s1 / (float)B_;
        }
    }

    // gather batch b's prompts: 2 tensors x 2 l x 5 k x 5 t rows of 192 float4
    const int ROWF4 = D_ / 4;                 // 192
    const int col = threadIdx.x;
#pragma unroll
    for (int tensor = 0; tensor < 2; ++tensor) {
        const float* srcbase = tensor ? tp : sp;
        float* outbase = out + (tensor ? OFF_TB : OFF_SB);
#pragma unroll
        for (int l = 0; l < L_; ++l) {
#pragma unroll
            for (int k = 0; k < TOPK_; ++k) {
                int idx = sidx[tensor][k];
                const float4* src = reinterpret_cast<const float4*>(
                    srcbase + ((size_t)((l * POOL_ + idx) * LEN_)) * D_) + col;
                float4* dst = reinterpret_cast<float4*>(
                    outbase + ((size_t)((l * B_ + b) * (TOPK_ * LEN_) + k * LEN_)) * D_) + col;
#pragma unroll
                for (int t = 0; t < LEN_; ++t) {
                    __stcs(&dst[t * ROWF4], __ldg(&src[t * ROWF4]));
                }
            }
        }
    }
}

// ---------------------------------------------------------------------------
extern "C" void kernel_launch(void* const* d_in, const int* in_sizes, int n_in,
                              void* d_out, int out_size) {
    (void)in_sizes; (void)n_in; (void)out_size;
    const float* x_embed  = (const float*)d_in[0];
    const float* s_prompt = (const float*)d_in[1];
    const float* t_prompt = (const float*)d_in[2];
    const float* s_key    = (const float*)d_in[3];
    const float* t_key    = (const float*)d_in[4];
    float* out = (float*)d_out;

    k_fused<<<dim3(B_, SS_), 192>>>(x_embed, s_key, t_key, s_prompt, t_prompt, out);
}

// round 8
// speedup vs baseline: 1.4538x; 1.4538x over previous
#include <cuda_runtime.h>
#include <cuda_bf16.h>
#include <math.h>

// Problem constants
#define B_     64
#define S_     2048
#define D_     768
#define L_     2
#define POOL_  30
#define LEN_   5
#define TOPK_  5
#define SS_    16           // S split count
#define SCHUNK_ (S_ / SS_)  // 128

// Output layout (flattened tuple, fp32):
#define NB_ELEMS   (L_ * B_ * (TOPK_*LEN_) * D_)   // 2457600
#define OFF_SB     0
#define OFF_TB     (NB_ELEMS)
#define OFF_SSIM   (2 * NB_ELEMS)
#define OFF_TSIM   (OFF_SSIM + B_ * POOL_)
#define OFF_SRED   (OFF_TSIM + B_ * POOL_)
#define OFF_TRED   (OFF_SRED + 1)

// Device scratch
__device__ float g_partial[SS_ * B_ * D_];   // 3 MB partial sums
__device__ float g_stop[B_];
__device__ float g_ttop[B_];
__device__ int   g_done;                     // completion counter (self-reset)

// ---------------------------------------------------------------------------
// Kernel A: partial mean over S chunks.  grid (B, SS), block 192.
// EXACTLY the R4 version: minimal registers (32) so unroll-16 keeps 16
// float4 loads in flight. Do not add code here.
// ---------------------------------------------------------------------------
__global__ void __launch_bounds__(192) k_mean_partial(const float* __restrict__ x) {
    int b  = blockIdx.x;
    int ss = blockIdx.y;
    int d4 = threadIdx.x;                     // 0..191, each owns 4 d's
    const float4* xp = reinterpret_cast<const float4*>(x)
                     + ((size_t)(b * S_ + ss * SCHUNK_)) * (D_ / 4) + d4;
    float4 acc = make_float4(0.f, 0.f, 0.f, 0.f);
#pragma unroll 16
    for (int s = 0; s < SCHUNK_; ++s) {
        float4 v = __ldcs(&xp[(size_t)s * (D_ / 4)]);
        acc.x += v.x; acc.y += v.y; acc.z += v.z; acc.w += v.w;
    }
    reinterpret_cast<float4*>(g_partial)[(ss * B_ + b) * (D_ / 4) + d4] = acc;
}

// ---------------------------------------------------------------------------
// Kernel B: per-(pool, batch) finalize + gather in ONE launch.
// grid 128 = (pool 2) x (batch 64); block 256 (8 warps).
// Each block: reduce batch b's partials -> normalize -> its pool's 30 dots
// -> top-5 -> write sims + per-batch topsum -> gather its pool's 50 rows.
// Last of the 128 arrivals emits the two reduce-sim scalars.
// ---------------------------------------------------------------------------
__global__ void __launch_bounds__(256) k_tail(const float* __restrict__ skey,
                                              const float* __restrict__ tkey,
                                              const float* __restrict__ sp,
                                              const float* __restrict__ tp,
                                              float* __restrict__ out) {
    __shared__ __align__(16) float xn[D_];
    __shared__ float sim[POOL_];
    __shared__ float red[8];
    __shared__ int   sidx[TOPK_];

    const int pool = blockIdx.x >> 6;         // 0 = s, 1 = t
    const int b    = blockIdx.x & 63;

    const float* keys    = pool ? tkey : skey;
    const float* prompts = pool ? tp : sp;
    float* outb          = out + (pool ? OFF_TB : OFF_SB);
    const int simoff     = pool ? OFF_TSIM : OFF_SSIM;

    // ---- mean over 16 partials (threads 0..191, float4 lanes) ----
    float sq = 0.f;
    if (threadIdx.x < 192) {
        const int d4 = threadIdx.x;
        float4 s = make_float4(0.f, 0.f, 0.f, 0.f);
#pragma unroll
        for (int s2 = 0; s2 < SS_; ++s2) {
            float4 v = reinterpret_cast<const float4*>(g_partial)[(s2 * B_ + b) * (D_ / 4) + d4];
            s.x += v.x; s.y += v.y; s.z += v.z; s.w += v.w;
        }
        const float scale = 1.f / (float)S_;
        s.x *= scale; s.y *= scale; s.z *= scale; s.w *= scale;
        reinterpret_cast<float4*>(xn)[d4] = s;
        sq = s.x * s.x + s.y * s.y + s.z * s.z + s.w * s.w;
    }
    __syncthreads();

    // block reduce (8 warps)
    const int lane = threadIdx.x & 31, w = threadIdx.x >> 5;
#pragma unroll
    for (int o = 16; o; o >>= 1) sq += __shfl_down_sync(0xffffffffu, sq, o);
    if (lane == 0) red[w] = sq;
    __syncthreads();
    if (w == 0) {
        float v = (lane < 8) ? red[lane] : 0.f;
#pragma unroll
        for (int o = 4; o; o >>= 1) v += __shfl_down_sync(0xffffffffu, v, o);
        if (lane == 0) red[0] = v;
    }
    __syncthreads();
    const float inv = rsqrtf(fmaxf(red[0], 1e-12f));
    if (threadIdx.x < 192) {
        float4 v = reinterpret_cast<float4*>(xn)[threadIdx.x];
        v.x *= inv; v.y *= inv; v.z *= inv; v.w *= inv;
        reinterpret_cast<float4*>(xn)[threadIdx.x] = v;
    }
    __syncthreads();

    // ---- 30 dots (warp per key, 8 warps round-robin); inline key norm ----
    for (int key = w; key < POOL_; key += 8) {
        const float* kp = keys + key * D_;
        float dot = 0.f, kk = 0.f;
#pragma unroll
        for (int i = 0; i < D_ / 32; ++i) {
            int d = lane + i * 32;
            float kv = __ldg(&kp[d]);
            dot += kv * xn[d];
            kk  += kv * kv;
        }
#pragma unroll
        for (int o = 16; o; o >>= 1) {
            dot += __shfl_down_sync(0xffffffffu, dot, o);
            kk  += __shfl_down_sync(0xffffffffu, kk, o);
        }
        if (lane == 0) {
            float sv = dot * rsqrtf(fmaxf(kk, 1e-12f));
            sim[key] = sv;
            out[simoff + b * POOL_ + key] = sv;
        }
    }
    __syncthreads();

    // ---- top-5 (thread 0); strict '>' keeps lowest index on ties ----
    if (threadIdx.x == 0) {
        float loc[POOL_];
#pragma unroll
        for (int i = 0; i < POOL_; ++i) loc[i] = sim[i];
        float topsum = 0.f;
#pragma unroll
        for (int k = 0; k < TOPK_; ++k) {
            int   bj = 0;
            float bv = loc[0];
#pragma unroll
            for (int i = 1; i < POOL_; ++i) {
                if (loc[i] > bv) { bv = loc[i]; bj = i; }
            }
            sidx[k] = bj;
            topsum += bv;
            loc[bj] = -INFINITY;
        }
        // publish per-batch topsum, then arrival; 128th arriver does scalars
        if (pool == 0) g_stop[b] = topsum; else g_ttop[b] = topsum;
        __threadfence();
        int old = atomicAdd(&g_done, 1);
        if (old == 2 * B_ - 1) {
            atomicExch(&g_done, 0);           // self-reset for graph replay
            __threadfence();
            float s0 = 0.f, s1 = 0.f;
            for (int i = 0; i < B_; ++i) {
                s0 += __ldcg(&g_stop[i]);
                s1 += __ldcg(&g_ttop[i]);
            }
            out[OFF_SRED] = s0 / (float)B_;
            out[OFF_TRED] = s1 / (float)B_;
        }
    }
    __syncthreads();

    // ---- gather this pool's 50 rows for batch b ----
    // rows: (l in 0..1) x (k in 0..4) x (t in 0..4); 192 float4 per row
    const int ROWF4 = D_ / 4;                           // 192
    const int TOT   = L_ * TOPK_ * LEN_ * ROWF4;        // 9600
    for (int i = threadIdx.x; i < TOT; i += 256) {
        int col = i % ROWF4;
        int row = i / ROWF4;                  // 0..49
        int l   = row / (TOPK_ * LEN_);       // /25
        int r2  = row % (TOPK_ * LEN_);
        int k   = r2 / LEN_;
        int t   = r2 % LEN_;
        int idx = sidx[k];
        const float4* src = reinterpret_cast<const float4*>(
            prompts + ((size_t)((l * POOL_ + idx) * LEN_ + t)) * D_);
        float4* dst = reinterpret_cast<float4*>(
            outb + ((size_t)((l * B_ + b) * (TOPK_ * LEN_) + r2)) * D_);
        __stcs(&dst[col], __ldg(&src[col]));
    }
}

// ---------------------------------------------------------------------------
extern "C" void kernel_launch(void* const* d_in, const int* in_sizes, int n_in,
                              void* d_out, int out_size) {
    (void)in_sizes; (void)n_in; (void)out_size;
    const float* x_embed  = (const float*)d_in[0];
    const float* s_prompt = (const float*)d_in[1];
    const float* t_prompt = (const float*)d_in[2];
    const float* s_key    = (const float*)d_in[3];
    const float* t_key    = (const float*)d_in[4];
    float* out = (float*)d_out;

    k_mean_partial<<<dim3(B_, SS_), 192>>>(x_embed);
    k_tail<<<2 * B_, 256>>>(s_key, t_key, s_prompt, t_prompt, out);
}

// round 10
// speedup vs baseline: 1.5058x; 1.0358x over previous
#include <cuda_runtime.h>
#include <cuda_bf16.h>
#include <math.h>

// Problem constants
#define B_     64
#define S_     2048
#define D_     768
#define L_     2
#define POOL_  30
#define LEN_   5
#define TOPK_  5
#define SS_    16           // S split count
#define SCHUNK_ (S_ / SS_)  // 128

// Output layout (flattened tuple, fp32):
#define NB_ELEMS   (L_ * B_ * (TOPK_*LEN_) * D_)   // 2457600
#define OFF_SB     0
#define OFF_TB     (NB_ELEMS)
#define OFF_SSIM   (2 * NB_ELEMS)
#define OFF_TSIM   (OFF_SSIM + B_ * POOL_)
#define OFF_SRED   (OFF_TSIM + B_ * POOL_)
#define OFF_TRED   (OFF_SRED + 1)

// Device scratch
__device__ float g_partial[SS_ * B_ * D_];   // 3 MB partial sums
__device__ int   g_idx[2][B_ * TOPK_];       // [pool][b*5+k]
__device__ float g_stop[B_];
__device__ float g_ttop[B_];

// ---------------------------------------------------------------------------
// Kernel A: partial mean over S chunks.  grid (B, SS), block 192.
// EXACTLY the R4 version (32 regs, 84% DRAM). Do not add code here.
// ---------------------------------------------------------------------------
__global__ void __launch_bounds__(192) k_mean_partial(const float* __restrict__ x) {
    int b  = blockIdx.x;
    int ss = blockIdx.y;
    int d4 = threadIdx.x;                     // 0..191, each owns 4 d's
    const float4* xp = reinterpret_cast<const float4*>(x)
                     + ((size_t)(b * S_ + ss * SCHUNK_)) * (D_ / 4) + d4;
    float4 acc = make_float4(0.f, 0.f, 0.f, 0.f);
#pragma unroll 16
    for (int s = 0; s < SCHUNK_; ++s) {
        float4 v = __ldcs(&xp[(size_t)s * (D_ / 4)]);
        acc.x += v.x; acc.y += v.y; acc.z += v.z; acc.w += v.w;
    }
    reinterpret_cast<float4*>(g_partial)[(ss * B_ + b) * (D_ / 4) + d4] = acc;
}

// ---------------------------------------------------------------------------
// Kernel B: sims + top-5 per (pool, batch).  grid 128, block 192 (6 warps).
// ---------------------------------------------------------------------------
__global__ void __launch_bounds__(192) k_sims(const float* __restrict__ skey,
                                              const float* __restrict__ tkey,
                                              float* __restrict__ out) {
    __shared__ __align__(16) float xn[D_];
    __shared__ float sim[POOL_];
    __shared__ float red[8];

    const int pool = blockIdx.x >> 6;         // 0 = s, 1 = t
    const int b    = blockIdx.x & 63;
    const float* keys = pool ? tkey : skey;
    const int simoff  = pool ? OFF_TSIM : OFF_SSIM;

    // mean over 16 partials (192 float4 lanes)
    const int d4 = threadIdx.x;
    float sq;
    {
        float4 s = make_float4(0.f, 0.f, 0.f, 0.f);
#pragma unroll
        for (int s2 = 0; s2 < SS_; ++s2) {
            float4 v = reinterpret_cast<const float4*>(g_partial)[(s2 * B_ + b) * (D_ / 4) + d4];
            s.x += v.x; s.y += v.y; s.z += v.z; s.w += v.w;
        }
        const float scale = 1.f / (float)S_;
        s.x *= scale; s.y *= scale; s.z *= scale; s.w *= scale;
        reinterpret_cast<float4*>(xn)[d4] = s;
        sq = s.x * s.x + s.y * s.y + s.z * s.z + s.w * s.w;
    }

    // block reduce over 6 warps
    const int lane = threadIdx.x & 31, w = threadIdx.x >> 5;
#pragma unroll
    for (int o = 16; o; o >>= 1) sq += __shfl_down_sync(0xffffffffu, sq, o);
    if (lane == 0) red[w] = sq;
    __syncthreads();
    if (w == 0) {
        float v = (lane < 6) ? red[lane] : 0.f;
#pragma unroll
        for (int o = 4; o; o >>= 1) v += __shfl_down_sync(0xffffffffu, v, o);
        if (lane == 0) red[0] = v;
    }
    __syncthreads();
    const float inv = rsqrtf(fmaxf(red[0], 1e-12f));
    {
        float4 v = reinterpret_cast<float4*>(xn)[d4];
        v.x *= inv; v.y *= inv; v.z *= inv; v.w *= inv;
        reinterpret_cast<float4*>(xn)[d4] = v;
    }
    __syncthreads();

    // 30 dots: warp per key round-robin (6 warps x 5 keys); inline key norm
    for (int key = w; key < POOL_; key += 6) {
        const float* kp = keys + key * D_;
        float dot = 0.f, kk = 0.f;
#pragma unroll
        for (int i = 0; i < D_ / 32; ++i) {
            int d = lane + i * 32;
            float kv = __ldg(&kp[d]);
            dot += kv * xn[d];
            kk  += kv * kv;
        }
#pragma unroll
        for (int o = 16; o; o >>= 1) {
            dot += __shfl_down_sync(0xffffffffu, dot, o);
            kk  += __shfl_down_sync(0xffffffffu, kk, o);
        }
        if (lane == 0) {
            float sv = dot * rsqrtf(fmaxf(kk, 1e-12f));
            sim[key] = sv;
            out[simoff + b * POOL_ + key] = sv;
        }
    }
    __syncthreads();

    // top-5 (thread 0); strict '>' keeps lowest index on ties
    if (threadIdx.x == 0) {
        float loc[POOL_];
#pragma unroll
        for (int i = 0; i < POOL_; ++i) loc[i] = sim[i];
        float topsum = 0.f;
#pragma unroll
        for (int k = 0; k < TOPK_; ++k) {
            int   bj = 0;
            float bv = loc[0];
#pragma unroll
            for (int i = 1; i < POOL_; ++i) {
                if (loc[i] > bv) { bv = loc[i]; bj = i; }
            }
            g_idx[pool][b * TOPK_ + k] = bj;
            topsum += bv;
            loc[bj] = -INFINITY;
        }
        if (pool == 0) g_stop[b] = topsum; else g_ttop[b] = topsum;
    }
}

// ---------------------------------------------------------------------------
// Kernel C: gather.  grid 1280 = (pool 2) x (b 64) x (l 2) x (k 5), block 192.
// Thread t owns float4 column t, copies 5 rows. Block 0 emits scalars.
// ---------------------------------------------------------------------------
__global__ void __launch_bounds__(192) k_gather(const float* __restrict__ sp,
                                                const float* __restrict__ tp,
                                                float* __restrict__ out) {
    const int bi   = blockIdx.x;
    const int k    = bi % TOPK_;
    const int l    = (bi / TOPK_) % L_;
    const int b    = (bi / (TOPK_ * L_)) % B_;
    const int pool = bi / (TOPK_ * L_ * B_);

    if (bi == 0 && threadIdx.x < 2) {
        const float* g = (threadIdx.x == 0) ? g_stop : g_ttop;
        float s = 0.f;
        for (int i = 0; i < B_; ++i) s += g[i];
        out[(threadIdx.x == 0) ? OFF_SRED : OFF_TRED] = s / (float)B_;
    }

    const int idx = g_idx[pool][b * TOPK_ + k];
    const float* prompts = pool ? tp : sp;
    float* outb = out + (pool ? OFF_TB : OFF_SB);

    const int ROWF4 = D_ / 4;   // 192
    const int col = threadIdx.x;
    const float4* src = reinterpret_cast<const float4*>(
        prompts + ((size_t)((l * POOL_ + idx) * LEN_)) * D_) + col;
    float4* dst = reinterpret_cast<float4*>(
        outb + ((size_t)((l * B_ + b) * (TOPK_ * LEN_) + k * LEN_)) * D_) + col;
#pragma unroll
    for (int t = 0; t < LEN_; ++t) {
        __stcs(&dst[t * ROWF4], __ldg(&src[t * ROWF4]));
    }
}

// ---------------------------------------------------------------------------
extern "C" void kernel_launch(void* const* d_in, const int* in_sizes, int n_in,
                              void* d_out, int out_size) {
    (void)in_sizes; (void)n_in; (void)out_size;
    const float* x_embed  = (const float*)d_in[0];
    const float* s_prompt = (const float*)d_in[1];
    const float* t_prompt = (const float*)d_in[2];
    const float* s_key    = (const float*)d_in[3];
    const float* t_key    = (const float*)d_in[4];
    float* out = (float*)d_out;

    k_mean_partial<<<dim3(B_, SS_), 192>>>(x_embed);
    k_sims<<<2 * B_, 192>>>(s_key, t_key, out);
    k_gather<<<2 * B_ * L_ * TOPK_, 192>>>(s_prompt, t_prompt, out);
}

// round 11
// speedup vs baseline: 1.5737x; 1.0451x over previous
#include <cuda_runtime.h>
#include <cuda_bf16.h>
#include <math.h>

// Problem constants
#define B_     64
#define S_     2048
#define D_     768
#define L_     2
#define POOL_  30
#define LEN_   5
#define TOPK_  5
#define SS_    16           // S split count
#define SCHUNK_ (S_ / SS_)  // 128

// Output layout (flattened tuple, fp32):
#define NB_ELEMS   (L_ * B_ * (TOPK_*LEN_) * D_)   // 2457600
#define OFF_SB     0
#define OFF_TB     (NB_ELEMS)
#define OFF_SSIM   (2 * NB_ELEMS)
#define OFF_TSIM   (OFF_SSIM + B_ * POOL_)
#define OFF_SRED   (OFF_TSIM + B_ * POOL_)
#define OFF_TRED   (OFF_SRED + 1)

// Device scratch
__device__ float g_partial[SS_ * B_ * D_];   // 3 MB partial sums
__device__ int   g_idx[2][B_ * TOPK_];       // [pool][b*5+k]
__device__ float g_stop[B_];
__device__ float g_ttop[B_];

// ---------------------------------------------------------------------------
// Kernel A: partial mean over S chunks.  grid (B, SS), block 192.
// R4 streaming body (32 regs target); PDL trigger after the partial store.
// ---------------------------------------------------------------------------
__global__ void __launch_bounds__(192) k_mean_partial(const float* __restrict__ x) {
    int b  = blockIdx.x;
    int ss = blockIdx.y;
    int d4 = threadIdx.x;                     // 0..191, each owns 4 d's
    const float4* xp = reinterpret_cast<const float4*>(x)
                     + ((size_t)(b * S_ + ss * SCHUNK_)) * (D_ / 4) + d4;
    float4 acc = make_float4(0.f, 0.f, 0.f, 0.f);
#pragma unroll 16
    for (int s = 0; s < SCHUNK_; ++s) {
        float4 v = __ldcs(&xp[(size_t)s * (D_ / 4)]);
        acc.x += v.x; acc.y += v.y; acc.z += v.z; acc.w += v.w;
    }
    reinterpret_cast<float4*>(g_partial)[(ss * B_ + b) * (D_ / 4) + d4] = acc;
    cudaTriggerProgrammaticLaunchCompletion();
}

// ---------------------------------------------------------------------------
// Kernel B: sims + top-5 per (pool, batch).  grid 128, block 192 (6 warps).
// PDL consumer of g_partial; PDL producer of g_idx/g_stop/g_ttop.
// ---------------------------------------------------------------------------
__global__ void __launch_bounds__(192) k_sims(const float* __restrict__ skey,
                                              const float* __restrict__ tkey,
                                              float* __restrict__ out) {
    __shared__ __align__(16) float xn[D_];
    __shared__ float sim[POOL_];
    __shared__ float red[8];

    const int pool = blockIdx.x >> 6;         // 0 = s, 1 = t
    const int b    = blockIdx.x & 63;
    const float* keys = pool ? tkey : skey;
    const int simoff  = pool ? OFF_TSIM : OFF_SSIM;

    // Wait for k_mean's stores to be visible, then reduce partials.
    cudaGridDependencySynchronize();

    const int d4 = threadIdx.x;
    float sq;
    {
        float4 s = make_float4(0.f, 0.f, 0.f, 0.f);
#pragma unroll
        for (int s2 = 0; s2 < SS_; ++s2) {
            float4 v = reinterpret_cast<const float4*>(g_partial)[(s2 * B_ + b) * (D_ / 4) + d4];
            s.x += v.x; s.y += v.y; s.z += v.z; s.w += v.w;
        }
        const float scale = 1.f / (float)S_;
        s.x *= scale; s.y *= scale; s.z *= scale; s.w *= scale;
        reinterpret_cast<float4*>(xn)[d4] = s;
        sq = s.x * s.x + s.y * s.y + s.z * s.z + s.w * s.w;
    }

    // block reduce over 6 warps
    const int lane = threadIdx.x & 31, w = threadIdx.x >> 5;
#pragma unroll
    for (int o = 16; o; o >>= 1) sq += __shfl_down_sync(0xffffffffu, sq, o);
    if (lane == 0) red[w] = sq;
    __syncthreads();
    if (w == 0) {
        float v = (lane < 6) ? red[lane] : 0.f;
#pragma unroll
        for (int o = 4; o; o >>= 1) v += __shfl_down_sync(0xffffffffu, v, o);
        if (lane == 0) red[0] = v;
    }
    __syncthreads();
    const float inv = rsqrtf(fmaxf(red[0], 1e-12f));
    {
        float4 v = reinterpret_cast<float4*>(xn)[d4];
        v.x *= inv; v.y *= inv; v.z *= inv; v.w *= inv;
        reinterpret_cast<float4*>(xn)[d4] = v;
    }
    __syncthreads();

    // 30 dots: warp per key round-robin (6 warps x 5 keys); inline key norm
    for (int key = w; key < POOL_; key += 6) {
        const float* kp = keys + key * D_;
        float dot = 0.f, kk = 0.f;
#pragma unroll
        for (int i = 0; i < D_ / 32; ++i) {
            int d = lane + i * 32;
            float kv = __ldg(&kp[d]);
            dot += kv * xn[d];
            kk  += kv * kv;
        }
#pragma unroll
        for (int o = 16; o; o >>= 1) {
            dot += __shfl_down_sync(0xffffffffu, dot, o);
            kk  += __shfl_down_sync(0xffffffffu, kk, o);
        }
        if (lane == 0) {
            float sv = dot * rsqrtf(fmaxf(kk, 1e-12f));
            sim[key] = sv;
            out[simoff + b * POOL_ + key] = sv;
        }
    }
    __syncthreads();

    // top-5 (thread 0); strict '>' keeps lowest index on ties
    if (threadIdx.x == 0) {
        float loc[POOL_];
#pragma unroll
        for (int i = 0; i < POOL_; ++i) loc[i] = sim[i];
        float topsum = 0.f;
#pragma unroll
        for (int k = 0; k < TOPK_; ++k) {
            int   bj = 0;
            float bv = loc[0];
#pragma unroll
            for (int i = 1; i < POOL_; ++i) {
                if (loc[i] > bv) { bv = loc[i]; bj = i; }
            }
            g_idx[pool][b * TOPK_ + k] = bj;
            topsum += bv;
            loc[bj] = -INFINITY;
        }
        if (pool == 0) g_stop[b] = topsum; else g_ttop[b] = topsum;
    }
    // Ensure g_idx/topsum writes precede every thread's trigger.
    __syncthreads();
    cudaTriggerProgrammaticLaunchCompletion();
}

// ---------------------------------------------------------------------------
// Kernel C: gather.  grid 1280 = (pool 2) x (b 64) x (l 2) x (k 5), block 192.
// PDL consumer of g_idx. Thread t owns float4 column t, copies 5 rows.
// Block 0 emits the reduce-sim scalars.
// ---------------------------------------------------------------------------
__global__ void __launch_bounds__(192) k_gather(const float* __restrict__ sp,
                                                const float* __restrict__ tp,
                                                float* __restrict__ out) {
    const int bi   = blockIdx.x;
    const int k    = bi % TOPK_;
    const int l    = (bi / TOPK_) % L_;
    const int b    = (bi / (TOPK_ * L_)) % B_;
    const int pool = bi / (TOPK_ * L_ * B_);

    cudaGridDependencySynchronize();

    if (bi == 0 && threadIdx.x < 2) {
        const float* g = (threadIdx.x == 0) ? g_stop : g_ttop;
        float s = 0.f;
        for (int i = 0; i < B_; ++i) s += g[i];
        out[(threadIdx.x == 0) ? OFF_SRED : OFF_TRED] = s / (float)B_;
    }

    const int idx = g_idx[pool][b * TOPK_ + k];
    const float* prompts = pool ? tp : sp;
    float* outb = out + (pool ? OFF_TB : OFF_SB);

    const int ROWF4 = D_ / 4;   // 192
    const int col = threadIdx.x;
    const float4* src = reinterpret_cast<const float4*>(
        prompts + ((size_t)((l * POOL_ + idx) * LEN_)) * D_) + col;
    float4* dst = reinterpret_cast<float4*>(
        outb + ((size_t)((l * B_ + b) * (TOPK_ * LEN_) + k * LEN_)) * D_) + col;
#pragma unroll
    for (int t = 0; t < LEN_; ++t) {
        __stcs(&dst[t * ROWF4], __ldg(&src[t * ROWF4]));
    }
}

// ---------------------------------------------------------------------------
// Launch with PDL edges: mean -> sims -> gather
// ---------------------------------------------------------------------------
static void launch_pdl(void* fn, dim3 grid, dim3 block, void** args) {
    cudaLaunchConfig_t cfg = {};
    cfg.gridDim = grid;
    cfg.blockDim = block;
    cfg.dynamicSmemBytes = 0;
    cfg.stream = 0;
    cudaLaunchAttribute attr[1];
    attr[0].id = cudaLaunchAttributeProgrammaticStreamSerialization;
    attr[0].val.programmaticStreamSerializationAllowed = 1;
    cfg.attrs = attr;
    cfg.numAttrs = 1;
    cudaLaunchKernelExC(&cfg, fn, args);
}

extern "C" void kernel_launch(void* const* d_in, const int* in_sizes, int n_in,
                              void* d_out, int out_size) {
    (void)in_sizes; (void)n_in; (void)out_size;
    const float* x_embed  = (const float*)d_in[0];
    const float* s_prompt = (const float*)d_in[1];
    const float* t_prompt = (const float*)d_in[2];
    const float* s_key    = (const float*)d_in[3];
    const float* t_key    = (const float*)d_in[4];
    float* out = (float*)d_out;

    // Primary launch (normal)
    k_mean_partial<<<dim3(B_, SS_), 192>>>(x_embed);

    // Dependent launches with programmatic stream serialization
    {
        void* args[] = { (void*)&s_key, (void*)&t_key, (void*)&out };
        launch_pdl((void*)k_sims, dim3(2 * B_), dim3(192), args);
    }
    {
        void* args[] = { (void*)&s_prompt, (void*)&t_prompt, (void*)&out };
        launch_pdl((void*)k_gather, dim3(2 * B_ * L_ * TOPK_), dim3(192), args);
    }
}